// round 15
// baseline (speedup 1.0000x reference)
#include <cuda_runtime.h>
#include <cuda_fp16.h>
#include <cstdint>
#include <math.h>

#define BB   4
#define NQ   1024
#define NKV  2048
#define CC   1024
#define NH   16
#define DH   64
#define HID  4096

// ---------------- scratch (device globals; allocation-guard safe) -----------
__device__ __half g_q16 [BB * NQ * CC];
__device__ __half g_xn16[BB * NKV * CC];
__device__ __half g_qh16[BB * NQ * CC];
__device__ __half g_kv16[BB * NKV * 2 * CC];
__device__ __half g_kT16[BB * CC * NKV];
__device__ __half g_y16 [BB * NQ * CC];
__device__ __half g_t16 [BB * NQ * CC];
__device__ __half g_hid16[BB * NQ * HID];
__device__ float  g_q2  [BB * NQ * CC];
__device__ float  g_rowsum[BB * NH * NQ];
__device__ __half g_wq16 [CC * CC];
__device__ __half g_wkv16[CC * 2 * CC];
__device__ __half g_wp16 [CC * CC];
__device__ __half g_w116 [CC * HID];
__device__ __half g_w216 [HID * CC];

// ---------------------------------------------------------------------------
__device__ __forceinline__ uint32_t smem_u32(const void* p) {
    uint32_t a;
    asm("{ .reg .u64 t; cvta.to.shared.u64 t, %1; cvt.u32.u64 %0, t; }" : "=r"(a) : "l"(p));
    return a;
}
__device__ __forceinline__ uint32_t packh2(float x, float y) {
    uint32_t u;
    asm("cvt.rn.f16x2.f32 %0, %1, %2;" : "=r"(u) : "f"(y), "f"(x));
    return u;
}
__device__ __forceinline__ void cpasync16(uint32_t dst, const void* src) {
    asm volatile("cp.async.ca.shared.global [%0], [%1], 16;" :: "r"(dst), "l"(src));
}
#define CP_COMMIT() asm volatile("cp.async.commit_group;" ::: "memory")
#define CP_WAIT(N)  asm volatile("cp.async.wait_group %0;" :: "n"(N) : "memory")

__device__ __forceinline__ void mma_f16(float* c, const uint32_t* a, const uint32_t* b) {
    asm volatile(
        "mma.sync.aligned.m16n8k16.row.col.f32.f16.f16.f32 "
        "{%0,%1,%2,%3}, {%4,%5,%6,%7}, {%8,%9}, {%0,%1,%2,%3};"
        : "+f"(c[0]), "+f"(c[1]), "+f"(c[2]), "+f"(c[3])
        : "r"(a[0]), "r"(a[1]), "r"(a[2]), "r"(a[3]), "r"(b[0]), "r"(b[1]));
}
#define LDSM_X4(r0, r1, r2, r3, addr) \
    asm volatile("ldmatrix.sync.aligned.m8n8.x4.shared.b16 {%0,%1,%2,%3}, [%4];" \
                 : "=r"(r0), "=r"(r1), "=r"(r2), "=r"(r3) : "r"(addr))
#define LDSM_X4T(r0, r1, r2, r3, addr) \
    asm volatile("ldmatrix.sync.aligned.m8n8.x4.trans.shared.b16 {%0,%1,%2,%3}, [%4];" \
                 : "=r"(r0), "=r"(r1), "=r"(r2), "=r"(r3) : "r"(addr))

// ---------------------------------------------------------------------------
// fp16 tensor-core GEMM, cp.async 3-stage pipeline (R8-proven).
// MODE 0: v=acc  2: v=acc+bias[n]+res  3: v=gelu(acc+bias[n])
// MODE 4: v=exp(acc*scale)/rowsum[row]  (res = rowsum base, [z*NQ + m])
// ---------------------------------------------------------------------------
template <int BN, int MODE, bool WF, bool WH>
__global__ __launch_bounds__(256) void mma_gemm_h(
    const __half* __restrict__ A, int lda, long saB, long saH,
    const __half* __restrict__ B, int ldb, long sbB, long sbH,
    float* __restrict__ Cf, __half* __restrict__ Ch, int ldc, long scB, long scH,
    int K, const float* __restrict__ bias,
    const float* __restrict__ res, int ldres, float scale)
{
    constexpr int S    = 3;
    constexpr int APH  = 40;
    constexpr int BPH  = BN + 8;
    constexpr int ABUF = 128 * APH * 2;
    constexpr int BBUF = 32 * BPH * 2;
    constexpr int STG  = ABUF + BBUF;
    constexpr int WC   = (BN == 128) ? 4 : 2;
    constexpr int WM   = (BN == 128) ? 64 : 32;
    constexpr int MT   = WM / 16;
    constexpr int NT   = 4;
    constexpr int BCH  = BN / 64;
    constexpr int BROWCH = BN / 8;

    extern __shared__ __align__(16) char smem[];
    const uint32_t sb0 = smem_u32(smem);

    const int tid  = threadIdx.x;
    const int wid  = tid >> 5;
    const int lane = tid & 31;
    const int wm   = (wid / WC) * WM;
    const int wn   = (wid % WC) * 32;

    const int z = blockIdx.z, zb = z >> 4, zh = z & 15;
    const int bm = blockIdx.y * 128, bn = blockIdx.x * BN;

    const __half* Ab = A + (long)zb * saB + (long)zh * saH + (size_t)bm * lda;
    const __half* Bb = B + (long)zb * sbB + (long)zh * sbH + bn;
    float*  Cfb = WF ? Cf + (long)zb * scB + (long)zh * scH + (size_t)bm * ldc + bn : nullptr;
    __half* Chb = WH ? Ch + (long)zb * scB + (long)zh * scH + (size_t)bm * ldc + bn : nullptr;
    const float* Rb = (MODE == 2) ? res + (size_t)bm * ldres + bn : nullptr;
    const float* Rv = (MODE == 4) ? res + (long)z * NQ + bm : nullptr;

    const int nchunk = K >> 5;

    auto issue = [&](int ci) {
        const int s = ci % S;
        const uint32_t sA = sb0 + s * STG;
        const uint32_t sB = sA + ABUF;
        const int k0 = ci * 32;
        #pragma unroll
        for (int u = 0; u < 2; u++) {
            int c = tid + u * 256;
            int row = c >> 2, col = c & 3;
            cpasync16(sA + row * 80 + col * 16,
                      Ab + (size_t)row * lda + k0 + col * 8);
        }
        #pragma unroll
        for (int u = 0; u < BCH; u++) {
            int c = tid + u * 256;
            int row = c / BROWCH, col = c % BROWCH;
            cpasync16(sB + row * (BPH * 2) + col * 16,
                      Bb + (size_t)(k0 + row) * ldb + col * 8);
        }
        CP_COMMIT();
    };

    #pragma unroll
    for (int s = 0; s < S - 1; s++)
        if (s < nchunk) issue(s);

    float acc[MT][NT][4];
    #pragma unroll
    for (int i = 0; i < MT; i++)
        #pragma unroll
        for (int j = 0; j < NT; j++)
            #pragma unroll
            for (int v = 0; v < 4; v++) acc[i][j][v] = 0.f;

    const int lr = ((lane >> 3) & 1) * 8 + (lane & 7);
    const int lc = ((lane >> 4) & 1) * 8;

    for (int ci = 0; ci < nchunk; ci++) {
        if (ci + 2 < nchunk) { CP_WAIT(1); } else { CP_WAIT(0); }
        __syncthreads();
        if (ci + 2 < nchunk) issue(ci + 2);

        const uint32_t sA = sb0 + (ci % S) * STG;
        const uint32_t sB = sA + ABUF;
        #pragma unroll
        for (int kk = 0; kk < 2; kk++) {
            uint32_t af[MT][4], bf[2][4];
            #pragma unroll
            for (int i = 0; i < MT; i++) {
                uint32_t addr = sA + (uint32_t)(((wm + 16 * i + lr) * APH + kk * 16 + lc) * 2);
                LDSM_X4(af[i][0], af[i][1], af[i][2], af[i][3], addr);
            }
            #pragma unroll
            for (int jj = 0; jj < 2; jj++) {
                uint32_t addr = sB + (uint32_t)(((kk * 16 + lr) * BPH + wn + 16 * jj + lc) * 2);
                LDSM_X4T(bf[jj][0], bf[jj][1], bf[jj][2], bf[jj][3], addr);
            }
            #pragma unroll
            for (int i = 0; i < MT; i++) {
                #pragma unroll
                for (int jj = 0; jj < 2; jj++) {
                    mma_f16(acc[i][2 * jj + 0], af[i], &bf[jj][0]);
                    mma_f16(acc[i][2 * jj + 1], af[i], &bf[jj][2]);
                }
            }
        }
        __syncthreads();
    }

    const int er = lane >> 2, ec = (lane & 3) * 2;
    #pragma unroll
    for (int i = 0; i < MT; i++) {
        #pragma unroll
        for (int rr = 0; rr < 2; rr++) {
            const int row = wm + 16 * i + er + 8 * rr;
            float*  Cfrow = WF ? Cfb + (size_t)row * ldc : nullptr;
            __half* Chrow = WH ? Chb + (size_t)row * ldc : nullptr;
            const float* Rrow = (MODE == 2) ? Rb + (size_t)row * ldres : nullptr;
            float inv = 0.f;
            if (MODE == 4) inv = 1.0f / Rv[row];
            #pragma unroll
            for (int j = 0; j < NT; j++) {
                const int col = wn + 8 * j + ec;
                float v0 = acc[i][j][2 * rr + 0];
                float v1 = acc[i][j][2 * rr + 1];
                if (MODE == 2) {
                    v0 += bias[bn + col]     + Rrow[col];
                    v1 += bias[bn + col + 1] + Rrow[col + 1];
                }
                if (MODE == 3) {
                    v0 += bias[bn + col];
                    v1 += bias[bn + col + 1];
                    v0 = 0.5f * v0 * (1.0f + erff(v0 * 0.70710678118654752f));
                    v1 = 0.5f * v1 * (1.0f + erff(v1 * 0.70710678118654752f));
                }
                if (MODE == 4) {
                    v0 = __expf(v0 * scale) * inv;
                    v1 = __expf(v1 * scale) * inv;
                }
                if (WF) *(float2*)&Cfrow[col] = make_float2(v0, v1);
                if (WH) *(uint32_t*)&Chrow[col] = packh2(v0, v1);
            }
        }
    }
}

// ---------------------------------------------------------------------------
// Fused attention (flash-style): per CTA = (128 q rows, one b*h). (R8-proven)
// ---------------------------------------------------------------------------
__global__ __launch_bounds__(256) void flash_fwd_kernel(
    const __half* __restrict__ qh, const __half* __restrict__ kT,
    const __half* __restrict__ kv, __half* __restrict__ y,
    float* __restrict__ rowsum)
{
    constexpr int QPH = 72;
    constexpr int KPH = 136;
    constexpr int VPH = 72;
    constexpr int QBUF = 128 * QPH * 2;
    constexpr int KBUF = 64 * KPH * 2;
    constexpr int VBUF = 128 * VPH * 2;

    extern __shared__ __align__(16) char smem[];
    const uint32_t sQ  = smem_u32(smem);
    const uint32_t sK0 = sQ + QBUF;
    const uint32_t sV0 = sK0 + 2 * KBUF;

    const int tid = threadIdx.x, wid = tid >> 5, lane = tid & 31;
    const int wm = wid * 16;
    const int qb = blockIdx.x, z = blockIdx.y;
    const int zb = z >> 4, zh = z & 15;

    const __half* Qg = qh + (size_t)zb * NQ * CC + zh * DH + (size_t)(qb * 128) * CC;
    const __half* Kg = kT + (size_t)zb * CC * NKV + (size_t)zh * DH * NKV;
    const __half* Vg = kv + (size_t)zb * NKV * 2 * CC + CC + zh * DH;

    #pragma unroll
    for (int u = 0; u < 4; u++) {
        int c = tid + u * 256;
        int row = c >> 3, col = c & 7;
        cpasync16(sQ + row * (QPH * 2) + col * 16, Qg + (size_t)row * CC + col * 8);
    }
    CP_COMMIT();

    auto issueKV = [&](int c) {
        const uint32_t dK = sK0 + (c & 1) * KBUF;
        const uint32_t dV = sV0 + (c & 1) * VBUF;
        #pragma unroll
        for (int u = 0; u < 4; u++) {
            int idx = tid + u * 256;
            int row = idx >> 4, col = idx & 15;
            cpasync16(dK + row * (KPH * 2) + col * 16,
                      Kg + (size_t)row * NKV + c * 128 + col * 8);
        }
        #pragma unroll
        for (int u = 0; u < 4; u++) {
            int idx = tid + u * 256;
            int row = idx >> 3, col = idx & 7;
            cpasync16(dV + row * (VPH * 2) + col * 16,
                      Vg + (size_t)(c * 128 + row) * (2 * CC) + col * 8);
        }
        CP_COMMIT();
    };
    issueKV(0);

    const int lr = ((lane >> 3) & 1) * 8 + (lane & 7);
    const int lc = ((lane >> 4) & 1) * 8;

    CP_WAIT(1);
    __syncthreads();
    uint32_t af[4][4];
    #pragma unroll
    for (int kst = 0; kst < 4; kst++) {
        uint32_t addr = sQ + (uint32_t)(((wm + lr) * QPH + kst * 16 + lc) * 2);
        LDSM_X4(af[kst][0], af[kst][1], af[kst][2], af[kst][3], addr);
    }

    float cacc[8][4];
    #pragma unroll
    for (int j = 0; j < 8; j++)
        #pragma unroll
        for (int v = 0; v < 4; v++) cacc[j][v] = 0.f;
    float rp0 = 0.f, rp1 = 0.f;

    for (int c = 0; c < 16; c++) {
        if (c + 1 < 16) { issueKV(c + 1); CP_WAIT(1); } else { CP_WAIT(0); }
        __syncthreads();
        const uint32_t sK = sK0 + (c & 1) * KBUF;
        const uint32_t sV = sV0 + (c & 1) * VBUF;

        float sacc[16][4];
        #pragma unroll
        for (int t = 0; t < 16; t++)
            #pragma unroll
            for (int v = 0; v < 4; v++) sacc[t][v] = 0.f;

        #pragma unroll
        for (int jj = 0; jj < 8; jj++) {
            #pragma unroll
            for (int kst = 0; kst < 4; kst++) {
                uint32_t bf[4];
                uint32_t addr = sK + (uint32_t)(((kst * 16 + lr) * KPH + jj * 16 + lc) * 2);
                LDSM_X4T(bf[0], bf[1], bf[2], bf[3], addr);
                mma_f16(sacc[2 * jj + 0], af[kst], &bf[0]);
                mma_f16(sacc[2 * jj + 1], af[kst], &bf[2]);
            }
        }

        uint32_t pf[8][4];
        #pragma unroll
        for (int jj = 0; jj < 8; jj++) {
            float e00 = __expf(sacc[2 * jj + 0][0] * 0.125f);
            float e01 = __expf(sacc[2 * jj + 0][1] * 0.125f);
            float e02 = __expf(sacc[2 * jj + 0][2] * 0.125f);
            float e03 = __expf(sacc[2 * jj + 0][3] * 0.125f);
            float e10 = __expf(sacc[2 * jj + 1][0] * 0.125f);
            float e11 = __expf(sacc[2 * jj + 1][1] * 0.125f);
            float e12 = __expf(sacc[2 * jj + 1][2] * 0.125f);
            float e13 = __expf(sacc[2 * jj + 1][3] * 0.125f);
            rp0 += e00 + e01 + e10 + e11;
            rp1 += e02 + e03 + e12 + e13;
            pf[jj][0] = packh2(e00, e01);
            pf[jj][1] = packh2(e02, e03);
            pf[jj][2] = packh2(e10, e11);
            pf[jj][3] = packh2(e12, e13);
        }

        #pragma unroll
        for (int jj = 0; jj < 8; jj++) {
            #pragma unroll
            for (int vv = 0; vv < 4; vv++) {
                uint32_t bv[4];
                uint32_t addr = sV + (uint32_t)(((jj * 16 + lr) * VPH + vv * 16 + lc) * 2);
                LDSM_X4T(bv[0], bv[1], bv[2], bv[3], addr);
                mma_f16(cacc[2 * vv + 0], pf[jj], &bv[0]);
                mma_f16(cacc[2 * vv + 1], pf[jj], &bv[2]);
            }
        }
        __syncthreads();
    }

    rp0 += __shfl_xor_sync(~0u, rp0, 1); rp0 += __shfl_xor_sync(~0u, rp0, 2);
    rp1 += __shfl_xor_sync(~0u, rp1, 1); rp1 += __shfl_xor_sync(~0u, rp1, 2);
    const int er = lane >> 2, ec = (lane & 3) * 2;
    const float inv0 = 1.0f / rp0, inv1 = 1.0f / rp1;

    __half* Yb = y + (size_t)zb * NQ * CC + (size_t)(qb * 128) * CC + zh * DH;
    __half* Yr0 = Yb + (size_t)(wm + er) * CC;
    __half* Yr1 = Yb + (size_t)(wm + er + 8) * CC;
    #pragma unroll
    for (int j = 0; j < 8; j++) {
        int col = 8 * j + ec;
        *(uint32_t*)&Yr0[col] = packh2(cacc[j][0] * inv0, cacc[j][1] * inv0);
        *(uint32_t*)&Yr1[col] = packh2(cacc[j][2] * inv1, cacc[j][3] * inv1);
    }
    if ((lane & 3) == 0) {
        rowsum[(size_t)z * NQ + qb * 128 + wm + er]     = rp0;
        rowsum[(size_t)z * NQ + qb * 128 + wm + er + 8] = rp1;
    }
}

// ---------------------------------------------------------------------------
// Batched fp32 -> fp16 conversion for 6 arrays in one launch.
// ---------------------------------------------------------------------------
__device__ __forceinline__ void cv4(const float* __restrict__ s, __half* __restrict__ d, long i) {
    float4 v = *(const float4*)(s + i);
    uint2 u = { packh2(v.x, v.y), packh2(v.z, v.w) };
    *(uint2*)(d + i) = u;
}
__global__ void f2h_multi(
    const float* __restrict__ s0, __half* __restrict__ d0, long n0,
    const float* __restrict__ s1, __half* __restrict__ d1, long n1,
    const float* __restrict__ s2, __half* __restrict__ d2, long n2,
    const float* __restrict__ s3, __half* __restrict__ d3, long n3,
    const float* __restrict__ s4, __half* __restrict__ d4, long n4,
    const float* __restrict__ s5, __half* __restrict__ d5, long n5)
{
    long i = ((long)blockIdx.x * blockDim.x + threadIdx.x) * 4;
    if (i < n0) { cv4(s0, d0, i); return; }  i -= n0;
    if (i < n1) { cv4(s1, d1, i); return; }  i -= n1;
    if (i < n2) { cv4(s2, d2, i); return; }  i -= n2;
    if (i < n3) { cv4(s3, d3, i); return; }  i -= n3;
    if (i < n4) { cv4(s4, d4, i); return; }  i -= n4;
    if (i < n5) { cv4(s5, d5, i); }
}

// ---------------------------------------------------------------------------
__global__ void transpose_h(const __half* __restrict__ in, int ld_in, long sb_in,
                            __half* __restrict__ out, int ld_out, long sb_out)
{
    __shared__ __half tile[32][34];
    const __half* ip = in + (long)blockIdx.z * sb_in;
    __half* op = out + (long)blockIdx.z * sb_out;
    int r0 = blockIdx.y * 32, c0 = blockIdx.x * 32;
    int x = threadIdx.x, y = threadIdx.y;
    #pragma unroll
    for (int j = 0; j < 32; j += 8)
        tile[y + j][x] = ip[(size_t)(r0 + y + j) * ld_in + c0 + x];
    __syncthreads();
    #pragma unroll
    for (int j = 0; j < 32; j += 8)
        op[(size_t)(c0 + y + j) * ld_out + r0 + x] = tile[x][y + j];
}

// ---------------------------------------------------------------------------
__global__ void ln_kernel_h(const float* __restrict__ x, const float* __restrict__ g,
                            const float* __restrict__ be, __half* __restrict__ out, int ccols)
{
    int row = blockIdx.x;
    const float* p = x + (size_t)row * ccols;
    __half* o = out + (size_t)row * ccols;
    int t = threadIdx.x;

    float s = 0.f, s2 = 0.f;
    for (int i = t; i < ccols; i += blockDim.x) { float v = p[i]; s += v; s2 += v * v; }
    __shared__ float r1[8], r2[8];
    #pragma unroll
    for (int off = 16; off; off >>= 1) {
        s  += __shfl_xor_sync(~0u, s,  off);
        s2 += __shfl_xor_sync(~0u, s2, off);
    }
    if ((t & 31) == 0) { r1[t >> 5] = s; r2[t >> 5] = s2; }
    __syncthreads();
    float ts = 0.f, ts2 = 0.f;
    #pragma unroll
    for (int i = 0; i < 8; i++) { ts += r1[i]; ts2 += r2[i]; }
    float mean = ts / ccols;
    float var  = ts2 / ccols - mean * mean;
    float inv  = rsqrtf(var + 1e-5f);
    for (int i = t; i < ccols; i += blockDim.x)
        o[i] = __float2half((p[i] - mean) * inv * g[i] + be[i]);
}

// ---------------------------------------------------------------------------
extern "C" void kernel_launch(void* const* d_in, const int* in_sizes, int n_in,
                              void* d_out, int out_size)
{
    const float* q     = (const float*)d_in[0];
    const float* x     = (const float*)d_in[1];
    const float* Wq    = (const float*)d_in[2];
    const float* Wkv   = (const float*)d_in[3];
    const float* Wproj = (const float*)d_in[4];
    const float* bproj = (const float*)d_in[5];
    const float* W1    = (const float*)d_in[6];
    const float* b1    = (const float*)d_in[7];
    const float* W2    = (const float*)d_in[8];
    const float* b2    = (const float*)d_in[9];
    const float* g1    = (const float*)d_in[10];
    const float* be1   = (const float*)d_in[11];
    const float* g2    = (const float*)d_in[12];
    const float* be2   = (const float*)d_in[13];

    float* out_q    = (float*)d_out;
    float* out_attn = out_q + (size_t)BB * NQ * CC;

    __half *q16, *xn16, *qh16, *kv16, *kT16, *y16, *t16, *hid16;
    __half *wq16, *wkv16, *wp16, *w116, *w216;
    float  *q2, *rowsum;
    cudaGetSymbolAddress((void**)&q16,  g_q16);
    cudaGetSymbolAddress((void**)&xn16, g_xn16);
    cudaGetSymbolAddress((void**)&qh16, g_qh16);
    cudaGetSymbolAddress((void**)&kv16, g_kv16);
    cudaGetSymbolAddress((void**)&kT16, g_kT16);
    cudaGetSymbolAddress((void**)&y16,  g_y16);
    cudaGetSymbolAddress((void**)&t16,  g_t16);
    cudaGetSymbolAddress((void**)&hid16,g_hid16);
    cudaGetSymbolAddress((void**)&q2,   g_q2);
    cudaGetSymbolAddress((void**)&rowsum, g_rowsum);
    cudaGetSymbolAddress((void**)&wq16, g_wq16);
    cudaGetSymbolAddress((void**)&wkv16,g_wkv16);
    cudaGetSymbolAddress((void**)&wp16, g_wp16);
    cudaGetSymbolAddress((void**)&w116, g_w116);
    cudaGetSymbolAddress((void**)&w216, g_w216);

    const int SM128 = 3 * (128 * 40 * 2 + 32 * 136 * 2);                 // 56832
    const int SMF   = 128 * 72 * 2 + 2 * (64 * 136 * 2) + 2 * (128 * 72 * 2);  // 90112
    cudaFuncSetAttribute((const void*)mma_gemm_h<128, 0, false, true>,  cudaFuncAttributeMaxDynamicSharedMemorySize, SM128);
    cudaFuncSetAttribute((const void*)mma_gemm_h<128, 2, true,  false>, cudaFuncAttributeMaxDynamicSharedMemorySize, SM128);
    cudaFuncSetAttribute((const void*)mma_gemm_h<128, 3, false, true>,  cudaFuncAttributeMaxDynamicSharedMemorySize, SM128);
    cudaFuncSetAttribute((const void*)mma_gemm_h<128, 4, true,  false>, cudaFuncAttributeMaxDynamicSharedMemorySize, SM128);
    cudaFuncSetAttribute((const void*)flash_fwd_kernel, cudaFuncAttributeMaxDynamicSharedMemorySize, SMF);

    // side stream + events for the capture-legal fork
    cudaStream_t s2;
    cudaStreamCreateWithFlags(&s2, cudaStreamNonBlocking);
    cudaEvent_t evFork, evJoin;
    cudaEventCreateWithFlags(&evFork, cudaEventDisableTiming);
    cudaEventCreateWithFlags(&evJoin, cudaEventDisableTiming);

    dim3 tb(32, 8);

    // 0) all fp16 conversions in ONE launch (16M elements / 4 per thread)
    {
        long n_q  = (long)BB * NQ * CC;
        long n_wq = (long)CC * CC;
        long n_wk = (long)CC * 2 * CC;
        long n_wp = (long)CC * CC;
        long n_w1 = (long)CC * HID;
        long n_w2 = (long)HID * CC;
        long total = n_q + n_wq + n_wk + n_wp + n_w1 + n_w2;  // 16M
        int blocks = (int)(total / 4 / 256);
        f2h_multi<<<blocks, 256>>>(q, q16, n_q, Wq, wq16, n_wq, Wkv, wkv16, n_wk,
                                   Wproj, wp16, n_wp, W1, w116, n_w1, W2, w216, n_w2);
    }

    // 1) xn16 = LN(x)
    ln_kernel_h<<<BB * NKV, 256>>>(x, g1, be1, xn16, CC);

    // 2) qh16 = q16 @ Wq16
    mma_gemm_h<128, 0, false, true><<<dim3(CC / 128, BB * NQ / 128, 1), 256, SM128>>>(
        q16, CC, 0, 0, wq16, CC, 0, 0, nullptr, qh16, CC, 0, 0, CC, nullptr, nullptr, 0, 0.f);

    // 3) kv16 = xn16 @ Wkv16
    mma_gemm_h<128, 0, false, true><<<dim3(2 * CC / 128, BB * NKV / 128, 1), 256, SM128>>>(
        xn16, CC, 0, 0, wkv16, 2 * CC, 0, 0, nullptr, kv16, 2 * CC, 0, 0, CC, nullptr, nullptr, 0, 0.f);

    // 4) kT16 = transpose of k-half of kv16
    transpose_h<<<dim3(CC / 32, NKV / 32, BB), tb>>>(
        kv16, 2 * CC, (long)NKV * 2 * CC, kT16, NKV, (long)CC * NKV);

    // 5) fused attention: rowsum + y16 = softmax(S) @ V
    flash_fwd_kernel<<<dim3(NQ / 128, BB * NH), 256, SMF>>>(
        qh16, kT16, kv16, y16, rowsum);

    // ---- fork: attn writer on s2, FFN chain on stream 0
    cudaEventRecord(evFork, 0);
    cudaStreamWaitEvent(s2, evFork, 0);

    // 6) [s2] attn = exp(s/8)/rowsum -> fp32 out_attn
    mma_gemm_h<128, 4, true, false><<<dim3(NKV / 128, NQ / 128, BB * NH), 256, SM128, s2>>>(
        qh16, CC, (long)NQ * CC, DH,
        kT16, NKV, (long)CC * NKV, (long)DH * NKV,
        out_attn, nullptr, NKV, (long)NH * NQ * NKV, (long)NQ * NKV,
        DH, nullptr, rowsum, 0, 0.125f);
    cudaEventRecord(evJoin, s2);

    // 7) [main] q2 = q + y16 @ Wp16 + bproj
    mma_gemm_h<128, 2, true, false><<<dim3(CC / 128, BB * NQ / 128, 1), 256, SM128>>>(
        y16, CC, 0, 0, wp16, CC, 0, 0, q2, nullptr, CC, 0, 0, CC, bproj, q, CC, 0.f);

    // 8) [main] t16 = LN(q2)
    ln_kernel_h<<<BB * NQ, 256>>>(q2, g2, be2, t16, CC);

    // 9) [main] hid16 = gelu(t16 @ W116 + b1)
    mma_gemm_h<128, 3, false, true><<<dim3(HID / 128, BB * NQ / 128, 1), 256, SM128>>>(
        t16, CC, 0, 0, w116, HID, 0, 0, nullptr, hid16, HID, 0, 0, CC, b1, nullptr, 0, 0.f);

    // 10) [main] out_q = q2 + hid16 @ W216 + b2
    mma_gemm_h<128, 2, true, false><<<dim3(CC / 128, BB * NQ / 128, 1), 256, SM128>>>(
        hid16, HID, 0, 0, w216, CC, 0, 0, out_q, nullptr, CC, 0, 0, HID, b2, q2, CC, 0.f);

    // ---- join: stream 0 waits for the attn writer before returning
    cudaStreamWaitEvent(0, evJoin, 0);
}

// round 17
// speedup vs baseline: 1.5308x; 1.5308x over previous
#include <cuda_runtime.h>
#include <cuda_fp16.h>
#include <cstdint>
#include <math.h>

#define BB   4
#define NQ   1024
#define NKV  2048
#define CC   1024
#define NH   16
#define DH   64
#define HID  4096

// ---------------- scratch (device globals; allocation-guard safe) -----------
__device__ __half g_q16 [BB * NQ * CC];
__device__ __half g_xn16[BB * NKV * CC];
__device__ __half g_qh16[BB * NQ * CC];
__device__ __half g_kv16[BB * NKV * 2 * CC];
__device__ __half g_kT16[BB * CC * NKV];
__device__ __half g_y16 [BB * NQ * CC];
__device__ __half g_t16 [BB * NQ * CC];
__device__ __half g_hid16[BB * NQ * HID];
__device__ float  g_q2  [BB * NQ * CC];
__device__ float  g_rowsum[BB * NH * NQ];
__device__ __half g_wq16 [CC * CC];
__device__ __half g_wkv16[CC * 2 * CC];
__device__ __half g_wp16 [CC * CC];
__device__ __half g_w116 [CC * HID];
__device__ __half g_w216 [HID * CC];

// ---------------------------------------------------------------------------
__device__ __forceinline__ uint32_t smem_u32(const void* p) {
    uint32_t a;
    asm("{ .reg .u64 t; cvta.to.shared.u64 t, %1; cvt.u32.u64 %0, t; }" : "=r"(a) : "l"(p));
    return a;
}
__device__ __forceinline__ uint32_t packh2(float x, float y) {
    uint32_t u;
    asm("cvt.rn.f16x2.f32 %0, %1, %2;" : "=r"(u) : "f"(y), "f"(x));
    return u;
}
__device__ __forceinline__ void cpasync16(uint32_t dst, const void* src) {
    asm volatile("cp.async.ca.shared.global [%0], [%1], 16;" :: "r"(dst), "l"(src));
}
#define CP_COMMIT() asm volatile("cp.async.commit_group;" ::: "memory")
#define CP_WAIT(N)  asm volatile("cp.async.wait_group %0;" :: "n"(N) : "memory")

__device__ __forceinline__ void mma_f16(float* c, const uint32_t* a, const uint32_t* b) {
    asm volatile(
        "mma.sync.aligned.m16n8k16.row.col.f32.f16.f16.f32 "
        "{%0,%1,%2,%3}, {%4,%5,%6,%7}, {%8,%9}, {%0,%1,%2,%3};"
        : "+f"(c[0]), "+f"(c[1]), "+f"(c[2]), "+f"(c[3])
        : "r"(a[0]), "r"(a[1]), "r"(a[2]), "r"(a[3]), "r"(b[0]), "r"(b[1]));
}
#define LDSM_X4(r0, r1, r2, r3, addr) \
    asm volatile("ldmatrix.sync.aligned.m8n8.x4.shared.b16 {%0,%1,%2,%3}, [%4];" \
                 : "=r"(r0), "=r"(r1), "=r"(r2), "=r"(r3) : "r"(addr))
#define LDSM_X4T(r0, r1, r2, r3, addr) \
    asm volatile("ldmatrix.sync.aligned.m8n8.x4.trans.shared.b16 {%0,%1,%2,%3}, [%4];" \
                 : "=r"(r0), "=r"(r1), "=r"(r2), "=r"(r3) : "r"(addr))

// ---------------------------------------------------------------------------
// fp16 tensor-core GEMM, cp.async 3-stage pipeline (R8-proven).
// MODE 0: v=acc  2: v=acc+bias[n]+res  3: v=gelu(acc+bias[n])
// MODE 4: v=exp(acc*scale)/rowsum[row]  (res = rowsum base, [z*NQ + m])
// ---------------------------------------------------------------------------
template <int BN, int MODE, bool WF, bool WH>
__global__ __launch_bounds__(256) void mma_gemm_h(
    const __half* __restrict__ A, int lda, long saB, long saH,
    const __half* __restrict__ B, int ldb, long sbB, long sbH,
    float* __restrict__ Cf, __half* __restrict__ Ch, int ldc, long scB, long scH,
    int K, const float* __restrict__ bias,
    const float* __restrict__ res, int ldres, float scale)
{
    constexpr int S    = 3;
    constexpr int APH  = 40;
    constexpr int BPH  = BN + 8;
    constexpr int ABUF = 128 * APH * 2;
    constexpr int BBUF = 32 * BPH * 2;
    constexpr int STG  = ABUF + BBUF;
    constexpr int WC   = (BN == 128) ? 4 : 2;
    constexpr int WM   = (BN == 128) ? 64 : 32;
    constexpr int MT   = WM / 16;
    constexpr int NT   = 4;
    constexpr int BCH  = BN / 64;
    constexpr int BROWCH = BN / 8;

    extern __shared__ __align__(16) char smem[];
    const uint32_t sb0 = smem_u32(smem);

    const int tid  = threadIdx.x;
    const int wid  = tid >> 5;
    const int lane = tid & 31;
    const int wm   = (wid / WC) * WM;
    const int wn   = (wid % WC) * 32;

    const int z = blockIdx.z, zb = z >> 4, zh = z & 15;
    const int bm = blockIdx.y * 128, bn = blockIdx.x * BN;

    const __half* Ab = A + (long)zb * saB + (long)zh * saH + (size_t)bm * lda;
    const __half* Bb = B + (long)zb * sbB + (long)zh * sbH + bn;
    float*  Cfb = WF ? Cf + (long)zb * scB + (long)zh * scH + (size_t)bm * ldc + bn : nullptr;
    __half* Chb = WH ? Ch + (long)zb * scB + (long)zh * scH + (size_t)bm * ldc + bn : nullptr;
    const float* Rb = (MODE == 2) ? res + (size_t)bm * ldres + bn : nullptr;
    const float* Rv = (MODE == 4) ? res + (long)z * NQ + bm : nullptr;

    const int nchunk = K >> 5;

    auto issue = [&](int ci) {
        const int s = ci % S;
        const uint32_t sA = sb0 + s * STG;
        const uint32_t sB = sA + ABUF;
        const int k0 = ci * 32;
        #pragma unroll
        for (int u = 0; u < 2; u++) {
            int c = tid + u * 256;
            int row = c >> 2, col = c & 3;
            cpasync16(sA + row * 80 + col * 16,
                      Ab + (size_t)row * lda + k0 + col * 8);
        }
        #pragma unroll
        for (int u = 0; u < BCH; u++) {
            int c = tid + u * 256;
            int row = c / BROWCH, col = c % BROWCH;
            cpasync16(sB + row * (BPH * 2) + col * 16,
                      Bb + (size_t)(k0 + row) * ldb + col * 8);
        }
        CP_COMMIT();
    };

    #pragma unroll
    for (int s = 0; s < S - 1; s++)
        if (s < nchunk) issue(s);

    float acc[MT][NT][4];
    #pragma unroll
    for (int i = 0; i < MT; i++)
        #pragma unroll
        for (int j = 0; j < NT; j++)
            #pragma unroll
            for (int v = 0; v < 4; v++) acc[i][j][v] = 0.f;

    const int lr = ((lane >> 3) & 1) * 8 + (lane & 7);
    const int lc = ((lane >> 4) & 1) * 8;

    for (int ci = 0; ci < nchunk; ci++) {
        if (ci + 2 < nchunk) { CP_WAIT(1); } else { CP_WAIT(0); }
        __syncthreads();
        if (ci + 2 < nchunk) issue(ci + 2);

        const uint32_t sA = sb0 + (ci % S) * STG;
        const uint32_t sB = sA + ABUF;
        #pragma unroll
        for (int kk = 0; kk < 2; kk++) {
            uint32_t af[MT][4], bf[2][4];
            #pragma unroll
            for (int i = 0; i < MT; i++) {
                uint32_t addr = sA + (uint32_t)(((wm + 16 * i + lr) * APH + kk * 16 + lc) * 2);
                LDSM_X4(af[i][0], af[i][1], af[i][2], af[i][3], addr);
            }
            #pragma unroll
            for (int jj = 0; jj < 2; jj++) {
                uint32_t addr = sB + (uint32_t)(((kk * 16 + lr) * BPH + wn + 16 * jj + lc) * 2);
                LDSM_X4T(bf[jj][0], bf[jj][1], bf[jj][2], bf[jj][3], addr);
            }
            #pragma unroll
            for (int i = 0; i < MT; i++) {
                #pragma unroll
                for (int jj = 0; jj < 2; jj++) {
                    mma_f16(acc[i][2 * jj + 0], af[i], &bf[jj][0]);
                    mma_f16(acc[i][2 * jj + 1], af[i], &bf[jj][2]);
                }
            }
        }
        __syncthreads();
    }

    const int er = lane >> 2, ec = (lane & 3) * 2;
    #pragma unroll
    for (int i = 0; i < MT; i++) {
        #pragma unroll
        for (int rr = 0; rr < 2; rr++) {
            const int row = wm + 16 * i + er + 8 * rr;
            float*  Cfrow = WF ? Cfb + (size_t)row * ldc : nullptr;
            __half* Chrow = WH ? Chb + (size_t)row * ldc : nullptr;
            const float* Rrow = (MODE == 2) ? Rb + (size_t)row * ldres : nullptr;
            float inv = 0.f;
            if (MODE == 4) inv = 1.0f / Rv[row];
            #pragma unroll
            for (int j = 0; j < NT; j++) {
                const int col = wn + 8 * j + ec;
                float v0 = acc[i][j][2 * rr + 0];
                float v1 = acc[i][j][2 * rr + 1];
                if (MODE == 2) {
                    v0 += bias[bn + col]     + Rrow[col];
                    v1 += bias[bn + col + 1] + Rrow[col + 1];
                }
                if (MODE == 3) {
                    v0 += bias[bn + col];
                    v1 += bias[bn + col + 1];
                    v0 = 0.5f * v0 * (1.0f + erff(v0 * 0.70710678118654752f));
                    v1 = 0.5f * v1 * (1.0f + erff(v1 * 0.70710678118654752f));
                }
                if (MODE == 4) {
                    v0 = __expf(v0 * scale) * inv;
                    v1 = __expf(v1 * scale) * inv;
                }
                if (WF) *(float2*)&Cfrow[col] = make_float2(v0, v1);
                if (WH) *(uint32_t*)&Chrow[col] = packh2(v0, v1);
            }
        }
    }
}

// ---------------------------------------------------------------------------
// Fused attention (flash-style): per CTA = (128 q rows, one b*h). (R8-proven)
// ---------------------------------------------------------------------------
__global__ __launch_bounds__(256) void flash_fwd_kernel(
    const __half* __restrict__ qh, const __half* __restrict__ kT,
    const __half* __restrict__ kv, __half* __restrict__ y,
    float* __restrict__ rowsum)
{
    constexpr int QPH = 72;
    constexpr int KPH = 136;
    constexpr int VPH = 72;
    constexpr int QBUF = 128 * QPH * 2;
    constexpr int KBUF = 64 * KPH * 2;
    constexpr int VBUF = 128 * VPH * 2;

    extern __shared__ __align__(16) char smem[];
    const uint32_t sQ  = smem_u32(smem);
    const uint32_t sK0 = sQ + QBUF;
    const uint32_t sV0 = sK0 + 2 * KBUF;

    const int tid = threadIdx.x, wid = tid >> 5, lane = tid & 31;
    const int wm = wid * 16;
    const int qb = blockIdx.x, z = blockIdx.y;
    const int zb = z >> 4, zh = z & 15;

    const __half* Qg = qh + (size_t)zb * NQ * CC + zh * DH + (size_t)(qb * 128) * CC;
    const __half* Kg = kT + (size_t)zb * CC * NKV + (size_t)zh * DH * NKV;
    const __half* Vg = kv + (size_t)zb * NKV * 2 * CC + CC + zh * DH;

    #pragma unroll
    for (int u = 0; u < 4; u++) {
        int c = tid + u * 256;
        int row = c >> 3, col = c & 7;
        cpasync16(sQ + row * (QPH * 2) + col * 16, Qg + (size_t)row * CC + col * 8);
    }
    CP_COMMIT();

    auto issueKV = [&](int c) {
        const uint32_t dK = sK0 + (c & 1) * KBUF;
        const uint32_t dV = sV0 + (c & 1) * VBUF;
        #pragma unroll
        for (int u = 0; u < 4; u++) {
            int idx = tid + u * 256;
            int row = idx >> 4, col = idx & 15;
            cpasync16(dK + row * (KPH * 2) + col * 16,
                      Kg + (size_t)row * NKV + c * 128 + col * 8);
        }
        #pragma unroll
        for (int u = 0; u < 4; u++) {
            int idx = tid + u * 256;
            int row = idx >> 3, col = idx & 7;
            cpasync16(dV + row * (VPH * 2) + col * 16,
                      Vg + (size_t)(c * 128 + row) * (2 * CC) + col * 8);
        }
        CP_COMMIT();
    };
    issueKV(0);

    const int lr = ((lane >> 3) & 1) * 8 + (lane & 7);
    const int lc = ((lane >> 4) & 1) * 8;

    CP_WAIT(1);
    __syncthreads();
    uint32_t af[4][4];
    #pragma unroll
    for (int kst = 0; kst < 4; kst++) {
        uint32_t addr = sQ + (uint32_t)(((wm + lr) * QPH + kst * 16 + lc) * 2);
        LDSM_X4(af[kst][0], af[kst][1], af[kst][2], af[kst][3], addr);
    }

    float cacc[8][4];
    #pragma unroll
    for (int j = 0; j < 8; j++)
        #pragma unroll
        for (int v = 0; v < 4; v++) cacc[j][v] = 0.f;
    float rp0 = 0.f, rp1 = 0.f;

    for (int c = 0; c < 16; c++) {
        if (c + 1 < 16) { issueKV(c + 1); CP_WAIT(1); } else { CP_WAIT(0); }
        __syncthreads();
        const uint32_t sK = sK0 + (c & 1) * KBUF;
        const uint32_t sV = sV0 + (c & 1) * VBUF;

        float sacc[16][4];
        #pragma unroll
        for (int t = 0; t < 16; t++)
            #pragma unroll
            for (int v = 0; v < 4; v++) sacc[t][v] = 0.f;

        #pragma unroll
        for (int jj = 0; jj < 8; jj++) {
            #pragma unroll
            for (int kst = 0; kst < 4; kst++) {
                uint32_t bf[4];
                uint32_t addr = sK + (uint32_t)(((kst * 16 + lr) * KPH + jj * 16 + lc) * 2);
                LDSM_X4T(bf[0], bf[1], bf[2], bf[3], addr);
                mma_f16(sacc[2 * jj + 0], af[kst], &bf[0]);
                mma_f16(sacc[2 * jj + 1], af[kst], &bf[2]);
            }
        }

        uint32_t pf[8][4];
        #pragma unroll
        for (int jj = 0; jj < 8; jj++) {
            float e00 = __expf(sacc[2 * jj + 0][0] * 0.125f);
            float e01 = __expf(sacc[2 * jj + 0][1] * 0.125f);
            float e02 = __expf(sacc[2 * jj + 0][2] * 0.125f);
            float e03 = __expf(sacc[2 * jj + 0][3] * 0.125f);
            float e10 = __expf(sacc[2 * jj + 1][0] * 0.125f);
            float e11 = __expf(sacc[2 * jj + 1][1] * 0.125f);
            float e12 = __expf(sacc[2 * jj + 1][2] * 0.125f);
            float e13 = __expf(sacc[2 * jj + 1][3] * 0.125f);
            rp0 += e00 + e01 + e10 + e11;
            rp1 += e02 + e03 + e12 + e13;
            pf[jj][0] = packh2(e00, e01);
            pf[jj][1] = packh2(e02, e03);
            pf[jj][2] = packh2(e10, e11);
            pf[jj][3] = packh2(e12, e13);
        }

        #pragma unroll
        for (int jj = 0; jj < 8; jj++) {
            #pragma unroll
            for (int vv = 0; vv < 4; vv++) {
                uint32_t bv[4];
                uint32_t addr = sV + (uint32_t)(((jj * 16 + lr) * VPH + vv * 16 + lc) * 2);
                LDSM_X4T(bv[0], bv[1], bv[2], bv[3], addr);
                mma_f16(cacc[2 * vv + 0], pf[jj], &bv[0]);
                mma_f16(cacc[2 * vv + 1], pf[jj], &bv[2]);
            }
        }
        __syncthreads();
    }

    rp0 += __shfl_xor_sync(~0u, rp0, 1); rp0 += __shfl_xor_sync(~0u, rp0, 2);
    rp1 += __shfl_xor_sync(~0u, rp1, 1); rp1 += __shfl_xor_sync(~0u, rp1, 2);
    const int er = lane >> 2, ec = (lane & 3) * 2;
    const float inv0 = 1.0f / rp0, inv1 = 1.0f / rp1;

    __half* Yb = y + (size_t)zb * NQ * CC + (size_t)(qb * 128) * CC + zh * DH;
    __half* Yr0 = Yb + (size_t)(wm + er) * CC;
    __half* Yr1 = Yb + (size_t)(wm + er + 8) * CC;
    #pragma unroll
    for (int j = 0; j < 8; j++) {
        int col = 8 * j + ec;
        *(uint32_t*)&Yr0[col] = packh2(cacc[j][0] * inv0, cacc[j][1] * inv0);
        *(uint32_t*)&Yr1[col] = packh2(cacc[j][2] * inv1, cacc[j][3] * inv1);
    }
    if ((lane & 3) == 0) {
        rowsum[(size_t)z * NQ + qb * 128 + wm + er]     = rp0;
        rowsum[(size_t)z * NQ + qb * 128 + wm + er + 8] = rp1;
    }
}

// ---------------------------------------------------------------------------
__global__ void f2h_kernel(const float* __restrict__ in, __half* __restrict__ out, int n)
{
    int i = (blockIdx.x * blockDim.x + threadIdx.x) * 4;
    if (i < n) {
        float4 v = *(const float4*)(in + i);
        uint2 u = { packh2(v.x, v.y), packh2(v.z, v.w) };
        *(uint2*)(out + i) = u;
    }
}

// ---------------------------------------------------------------------------
__global__ void transpose_h(const __half* __restrict__ in, int ld_in, long sb_in,
                            __half* __restrict__ out, int ld_out, long sb_out)
{
    __shared__ __half tile[32][34];
    const __half* ip = in + (long)blockIdx.z * sb_in;
    __half* op = out + (long)blockIdx.z * sb_out;
    int r0 = blockIdx.y * 32, c0 = blockIdx.x * 32;
    int x = threadIdx.x, y = threadIdx.y;
    #pragma unroll
    for (int j = 0; j < 32; j += 8)
        tile[y + j][x] = ip[(size_t)(r0 + y + j) * ld_in + c0 + x];
    __syncthreads();
    #pragma unroll
    for (int j = 0; j < 32; j += 8)
        op[(size_t)(c0 + y + j) * ld_out + r0 + x] = tile[x][y + j];
}

// ---------------------------------------------------------------------------
// LayerNorm over last dim -> fp16, float4 loads (ccols multiple of 4*blockDim)
// ---------------------------------------------------------------------------
__global__ void ln_kernel_h(const float* __restrict__ x, const float* __restrict__ g,
                            const float* __restrict__ be, __half* __restrict__ out, int ccols)
{
    int row = blockIdx.x;
    const float* p = x + (size_t)row * ccols;
    __half* o = out + (size_t)row * ccols;
    int t = threadIdx.x;

    float s = 0.f, s2 = 0.f;
    float4 vv[4];
    int nv = 0;
    for (int i = t * 4; i < ccols; i += blockDim.x * 4) {
        float4 v = *(const float4*)(p + i);
        vv[nv++] = v;
        s  += v.x + v.y + v.z + v.w;
        s2 += v.x * v.x + v.y * v.y + v.z * v.z + v.w * v.w;
    }
    __shared__ float r1[8], r2[8];
    #pragma unroll
    for (int off = 16; off; off >>= 1) {
        s  += __shfl_xor_sync(~0u, s,  off);
        s2 += __shfl_xor_sync(~0u, s2, off);
    }
    if ((t & 31) == 0) { r1[t >> 5] = s; r2[t >> 5] = s2; }
    __syncthreads();
    float ts = 0.f, ts2 = 0.f;
    #pragma unroll
    for (int i = 0; i < 8; i++) { ts += r1[i]; ts2 += r2[i]; }
    float mean = ts / ccols;
    float var  = ts2 / ccols - mean * mean;
    float inv  = rsqrtf(var + 1e-5f);

    nv = 0;
    for (int i = t * 4; i < ccols; i += blockDim.x * 4) {
        float4 v = vv[nv++];
        float4 gg = *(const float4*)(g + i);
        float4 bb = *(const float4*)(be + i);
        float o0 = (v.x - mean) * inv * gg.x + bb.x;
        float o1 = (v.y - mean) * inv * gg.y + bb.y;
        float o2 = (v.z - mean) * inv * gg.z + bb.z;
        float o3 = (v.w - mean) * inv * gg.w + bb.w;
        uint2 u = { packh2(o0, o1), packh2(o2, o3) };
        *(uint2*)(o + i) = u;
    }
}

// ---------------------------------------------------------------------------
extern "C" void kernel_launch(void* const* d_in, const int* in_sizes, int n_in,
                              void* d_out, int out_size)
{
    const float* q     = (const float*)d_in[0];
    const float* x     = (const float*)d_in[1];
    const float* Wq    = (const float*)d_in[2];
    const float* Wkv   = (const float*)d_in[3];
    const float* Wproj = (const float*)d_in[4];
    const float* bproj = (const float*)d_in[5];
    const float* W1    = (const float*)d_in[6];
    const float* b1    = (const float*)d_in[7];
    const float* W2    = (const float*)d_in[8];
    const float* b2    = (const float*)d_in[9];
    const float* g1    = (const float*)d_in[10];
    const float* be1   = (const float*)d_in[11];
    const float* g2    = (const float*)d_in[12];
    const float* be2   = (const float*)d_in[13];

    float* out_q    = (float*)d_out;
    float* out_attn = out_q + (size_t)BB * NQ * CC;

    __half *q16, *xn16, *qh16, *kv16, *kT16, *y16, *t16, *hid16;
    __half *wq16, *wkv16, *wp16, *w116, *w216;
    float  *q2, *rowsum;
    cudaGetSymbolAddress((void**)&q16,  g_q16);
    cudaGetSymbolAddress((void**)&xn16, g_xn16);
    cudaGetSymbolAddress((void**)&qh16, g_qh16);
    cudaGetSymbolAddress((void**)&kv16, g_kv16);
    cudaGetSymbolAddress((void**)&kT16, g_kT16);
    cudaGetSymbolAddress((void**)&y16,  g_y16);
    cudaGetSymbolAddress((void**)&t16,  g_t16);
    cudaGetSymbolAddress((void**)&hid16,g_hid16);
    cudaGetSymbolAddress((void**)&q2,   g_q2);
    cudaGetSymbolAddress((void**)&rowsum, g_rowsum);
    cudaGetSymbolAddress((void**)&wq16, g_wq16);
    cudaGetSymbolAddress((void**)&wkv16,g_wkv16);
    cudaGetSymbolAddress((void**)&wp16, g_wp16);
    cudaGetSymbolAddress((void**)&w116, g_w116);
    cudaGetSymbolAddress((void**)&w216, g_w216);

    const int SM128 = 3 * (128 * 40 * 2 + 32 * 136 * 2);                 // 56832
    const int SMF   = 128 * 72 * 2 + 2 * (64 * 136 * 2) + 2 * (128 * 72 * 2);  // 90112
    cudaFuncSetAttribute((const void*)mma_gemm_h<128, 0, false, true>,  cudaFuncAttributeMaxDynamicSharedMemorySize, SM128);
    cudaFuncSetAttribute((const void*)mma_gemm_h<128, 2, true,  false>, cudaFuncAttributeMaxDynamicSharedMemorySize, SM128);
    cudaFuncSetAttribute((const void*)mma_gemm_h<128, 3, false, true>,  cudaFuncAttributeMaxDynamicSharedMemorySize, SM128);
    cudaFuncSetAttribute((const void*)mma_gemm_h<128, 4, true,  false>, cudaFuncAttributeMaxDynamicSharedMemorySize, SM128);
    cudaFuncSetAttribute((const void*)flash_fwd_kernel, cudaFuncAttributeMaxDynamicSharedMemorySize, SMF);

    // side stream + events for the capture-legal fork
    cudaStream_t s2;
    cudaStreamCreateWithFlags(&s2, cudaStreamNonBlocking);
    cudaEvent_t evFork, evJoin;
    cudaEventCreateWithFlags(&evFork, cudaEventDisableTiming);
    cudaEventCreateWithFlags(&evJoin, cudaEventDisableTiming);

    dim3 tb(32, 8);

    // 0) fp16 conversions (weights + q) — six launches (R13-proven)
    f2h_kernel<<<(BB * NQ * CC) / 1024, 256>>>(q,  q16,  BB * NQ * CC);
    f2h_kernel<<<(CC * CC) / 1024, 256>>>(Wq,    wq16,  CC * CC);
    f2h_kernel<<<(CC * 2 * CC) / 1024, 256>>>(Wkv, wkv16, CC * 2 * CC);
    f2h_kernel<<<(CC * CC) / 1024, 256>>>(Wproj, wp16,  CC * CC);
    f2h_kernel<<<(CC * HID) / 1024, 256>>>(W1,   w116,  CC * HID);
    f2h_kernel<<<(HID * CC) / 1024, 256>>>(W2,   w216,  HID * CC);

    // 1) xn16 = LN(x)
    ln_kernel_h<<<BB * NKV, 256>>>(x, g1, be1, xn16, CC);

    // 2) qh16 = q16 @ Wq16
    mma_gemm_h<128, 0, false, true><<<dim3(CC / 128, BB * NQ / 128, 1), 256, SM128>>>(
        q16, CC, 0, 0, wq16, CC, 0, 0, nullptr, qh16, CC, 0, 0, CC, nullptr, nullptr, 0, 0.f);

    // 3) kv16 = xn16 @ Wkv16
    mma_gemm_h<128, 0, false, true><<<dim3(2 * CC / 128, BB * NKV / 128, 1), 256, SM128>>>(
        xn16, CC, 0, 0, wkv16, 2 * CC, 0, 0, nullptr, kv16, 2 * CC, 0, 0, CC, nullptr, nullptr, 0, 0.f);

    // 4) kT16 = transpose of k-half of kv16
    transpose_h<<<dim3(CC / 32, NKV / 32, BB), tb>>>(
        kv16, 2 * CC, (long)NKV * 2 * CC, kT16, NKV, (long)CC * NKV);

    // 5) fused attention: rowsum + y16 = softmax(S) @ V
    flash_fwd_kernel<<<dim3(NQ / 128, BB * NH), 256, SMF>>>(
        qh16, kT16, kv16, y16, rowsum);

    // ---- fork: attn writer on s2, FFN chain on stream 0
    cudaEventRecord(evFork, 0);
    cudaStreamWaitEvent(s2, evFork, 0);

    // 6) [s2] attn = exp(s/8)/rowsum -> fp32 out_attn
    mma_gemm_h<128, 4, true, false><<<dim3(NKV / 128, NQ / 128, BB * NH), 256, SM128, s2>>>(
        qh16, CC, (long)NQ * CC, DH,
        kT16, NKV, (long)CC * NKV, (long)DH * NKV,
        out_attn, nullptr, NKV, (long)NH * NQ * NKV, (long)NQ * NKV,
        DH, nullptr, rowsum, 0, 0.125f);
    cudaEventRecord(evJoin, s2);

    // 7) [main] q2 = q + y16 @ Wp16 + bproj
    mma_gemm_h<128, 2, true, false><<<dim3(CC / 128, BB * NQ / 128, 1), 256, SM128>>>(
        y16, CC, 0, 0, wp16, CC, 0, 0, q2, nullptr, CC, 0, 0, CC, bproj, q, CC, 0.f);

    // 8) [main] t16 = LN(q2)
    ln_kernel_h<<<BB * NQ, 256>>>(q2, g2, be2, t16, CC);

    // 9) [main] hid16 = gelu(t16 @ W116 + b1)
    mma_gemm_h<128, 3, false, true><<<dim3(HID / 128, BB * NQ / 128, 1), 256, SM128>>>(
        t16, CC, 0, 0, w116, HID, 0, 0, nullptr, hid16, HID, 0, 0, CC, b1, nullptr, 0, 0.f);

    // 10) [main] out_q = q2 + hid16 @ W216 + b2
    mma_gemm_h<128, 2, true, false><<<dim3(CC / 128, BB * NQ / 128, 1), 256, SM128>>>(
        hid16, HID, 0, 0, w216, CC, 0, 0, out_q, nullptr, CC, 0, 0, HID, b2, q2, CC, 0.f);

    // ---- join: stream 0 waits for the attn writer before returning
    cudaStreamWaitEvent(0, evJoin, 0);
}